// round 2
// baseline (speedup 1.0000x reference)
#include <cuda_runtime.h>

#define N_NODES 16384
#define SZ 128
#define KNB 32

// ---------------- scratch (static device globals; no allocation) -----------
__device__ float g_h1[N_NODES * SZ];
__device__ float g_h2[N_NODES * SZ];
__device__ float g_msg[N_NODES * SZ];
__device__ float g_q[N_NODES * SZ];
__device__ float g_mk[N_NODES * SZ];
__device__ float g_mv[N_NODES * SZ];

// ---------------- dense 128-dim GEMM: C[N,128] = f(A[N,128] @ W[128,128] + b) (+ add)
// BM=64, BN=128, BK=32, 256 threads, each thread 8x4 outputs.
template <int RELU_IN, int RELU_OUT, int HAS_BIAS, int HAS_ADD>
__global__ __launch_bounds__(256) void gemm128(
    const float* __restrict__ A, const float* __restrict__ W,
    const float* __restrict__ bias, const float* __restrict__ add,
    float* __restrict__ C)
{
    __shared__ float As[32 * 64];    // [k][row]
    __shared__ float Ws[32 * 128];   // [k][col]
    const int t = threadIdx.x;
    const int tx = t & 31;           // col group: cols tx*4 .. tx*4+3
    const int ty = t >> 5;           // row group: rows ty*8 .. ty*8+7
    const int row0 = blockIdx.x * 64;

    float acc[8][4];
#pragma unroll
    for (int r = 0; r < 8; r++)
#pragma unroll
        for (int c = 0; c < 4; c++) acc[r][c] = 0.0f;

    for (int kt = 0; kt < 4; kt++) {
        const int kk0 = kt * 32;
        __syncthreads();
        // load A tile 64x32 (store transposed [k][row])
#pragma unroll
        for (int i = 0; i < 2; i++) {
            int f = t + i * 256;
            int r = f >> 3, c4 = f & 7;
            float4 v = *(const float4*)(A + (row0 + r) * 128 + kk0 + c4 * 4);
            if (RELU_IN) {
                v.x = fmaxf(v.x, 0.0f); v.y = fmaxf(v.y, 0.0f);
                v.z = fmaxf(v.z, 0.0f); v.w = fmaxf(v.w, 0.0f);
            }
            As[(c4 * 4 + 0) * 64 + r] = v.x;
            As[(c4 * 4 + 1) * 64 + r] = v.y;
            As[(c4 * 4 + 2) * 64 + r] = v.z;
            As[(c4 * 4 + 3) * 64 + r] = v.w;
        }
        // load W tile 32x128
#pragma unroll
        for (int i = 0; i < 4; i++) {
            int f = t + i * 256;
            int kr = f >> 5, c4 = f & 31;
            *(float4*)(Ws + kr * 128 + c4 * 4) =
                *(const float4*)(W + (kk0 + kr) * 128 + c4 * 4);
        }
        __syncthreads();
#pragma unroll
        for (int kk = 0; kk < 32; kk++) {
            float4 a0 = *(const float4*)(As + kk * 64 + ty * 8);
            float4 a1 = *(const float4*)(As + kk * 64 + ty * 8 + 4);
            float4 w  = *(const float4*)(Ws + kk * 128 + tx * 4);
            float ar[8] = {a0.x, a0.y, a0.z, a0.w, a1.x, a1.y, a1.z, a1.w};
#pragma unroll
            for (int r = 0; r < 8; r++) {
                acc[r][0] += ar[r] * w.x;
                acc[r][1] += ar[r] * w.y;
                acc[r][2] += ar[r] * w.z;
                acc[r][3] += ar[r] * w.w;
            }
        }
    }

    float4 bz = make_float4(0.f, 0.f, 0.f, 0.f);
    if (HAS_BIAS) bz = *(const float4*)(bias + tx * 4);
#pragma unroll
    for (int r = 0; r < 8; r++) {
        int gr = row0 + ty * 8 + r;
        float4 o;
        o.x = acc[r][0] + bz.x;
        o.y = acc[r][1] + bz.y;
        o.z = acc[r][2] + bz.z;
        o.w = acc[r][3] + bz.w;
        if (RELU_OUT) {
            o.x = fmaxf(o.x, 0.0f); o.y = fmaxf(o.y, 0.0f);
            o.z = fmaxf(o.z, 0.0f); o.w = fmaxf(o.w, 0.0f);
        }
        if (HAS_ADD) {
            float4 av = *(const float4*)(add + gr * 128 + tx * 4);
            o.x += av.x; o.y += av.y; o.z += av.z; o.w += av.w;
        }
        *(float4*)(C + gr * 128 + tx * 4) = o;
    }
}

// ---------------- per-node attention: 1 warp per node, lane <-> neighbor (K=32)
struct WarpSmem {
    float q[128];
    float dist[32 * 33];   // [k][d], pad 33
    float seq[32 * 17];    // [k][s], pad 17
    float ud[8 * 32];      // u_dist[h][d] = WkD^T q  per head
    float us[8 * 16];      // u_seq[h][s]
    float c0[8];           // q . bk  per head
    float attn[32 * 9];    // [k][h], pad 9
    float sd[8 * 32];      // sum_k attn*dist
    float ss[8 * 16];      // sum_k attn*seq
    float outv[128];
    int   jb[32];
};

__global__ __launch_bounds__(128) void attn_kernel(
    const float* __restrict__ features, const float* __restrict__ dist_g,
    const float* __restrict__ seq_g, const int* __restrict__ idx,
    const float* __restrict__ qg, const float* __restrict__ mkg,
    const float* __restrict__ mvg, const float* __restrict__ Wk,
    const float* __restrict__ bk, const float* __restrict__ Wv,
    const float* __restrict__ bv, const float* __restrict__ Wo,
    const float* __restrict__ bo, float* __restrict__ out)
{
    __shared__ WarpSmem S[4];
    const int lane = threadIdx.x & 31;
    const int w = threadIdx.x >> 5;
    WarpSmem& s = S[w];
    const int n = blockIdx.x * 4 + w;

    // ---- Phase A: stage per-node data
    for (int i = lane; i < 128; i += 32) s.q[i] = qg[n * 128 + i];
    s.jb[lane] = idx[n * 32 + lane];
#pragma unroll
    for (int it = 0; it < 32; it++)
        s.dist[it * 33 + lane] = dist_g[n * 1024 + it * 32 + lane];
#pragma unroll
    for (int it = 0; it < 16; it++) {
        int f = lane + 32 * it;            // f = k*16 + sc
        int k = f >> 4, sc = f & 15;
        s.seq[k * 17 + sc] = seq_g[n * 512 + f];
    }
    __syncwarp();

    // ---- Phase B: u = W^T q folds (dist / seq / bias)
#pragma unroll
    for (int r = 0; r < 8; r++) {
        int o = lane + 32 * r;             // o = h*32+d with h=r, d=lane
        int h = o >> 5, d = o & 31;
        const float* wr = Wk + (128 + d) * 128 + h * 16;
        const float* qh = s.q + h * 16;
        float a = 0.f;
#pragma unroll
        for (int j = 0; j < 16; j++) a += wr[j] * qh[j];
        s.ud[o] = a;
    }
#pragma unroll
    for (int r = 0; r < 4; r++) {
        int o = lane + 32 * r;             // o = h*16+sc
        int h = o >> 4, sc = o & 15;
        const float* wr = Wk + (160 + sc) * 128 + h * 16;
        const float* qh = s.q + h * 16;
        float a = 0.f;
#pragma unroll
        for (int j = 0; j < 16; j++) a += wr[j] * qh[j];
        s.us[o] = a;
    }
    if (lane < 8) {
        const float* qh = s.q + lane * 16;
        const float* br = bk + lane * 16;
        float a = 0.f;
#pragma unroll
        for (int j = 0; j < 16; j++) a += br[j] * qh[j];
        s.c0[lane] = a;
    }
    __syncwarp();

    // ---- Phase C: logits (lane = neighbor k) + softmax over lanes
    float dr[32], sr[16];
#pragma unroll
    for (int d = 0; d < 32; d++) dr[d] = s.dist[lane * 33 + d];
#pragma unroll
    for (int j = 0; j < 16; j++) sr[j] = s.seq[lane * 17 + j];
    const int jrow = s.jb[lane];
    const float4* mk4 = (const float4*)(mkg + (long)jrow * 128);
    float lg[8];
#pragma unroll
    for (int h = 0; h < 8; h++) lg[h] = 0.f;
#pragma unroll
    for (int i4 = 0; i4 < 32; i4++) {
        float4 m = mk4[i4];
        int h = i4 >> 2, i0 = i4 * 4;
        lg[h] += s.q[i0] * m.x + s.q[i0 + 1] * m.y +
                 s.q[i0 + 2] * m.z + s.q[i0 + 3] * m.w;
    }
#pragma unroll
    for (int h = 0; h < 8; h++) {
        float a = 0.f;
#pragma unroll
        for (int d = 0; d < 32; d++) a += dr[d] * s.ud[h * 32 + d];
#pragma unroll
        for (int j = 0; j < 16; j++) a += sr[j] * s.us[h * 16 + j];
        lg[h] = 0.25f * (lg[h] + a + s.c0[h]);
    }
#pragma unroll
    for (int h = 0; h < 8; h++) {
        float m = lg[h];
#pragma unroll
        for (int o = 16; o > 0; o >>= 1) m = fmaxf(m, __shfl_xor_sync(~0u, m, o));
        float e = __expf(lg[h] - m);
        float sm = e;
#pragma unroll
        for (int o = 16; o > 0; o >>= 1) sm += __shfl_xor_sync(~0u, sm, o);
        s.attn[lane * 9 + h] = e / sm;
    }
    __syncwarp();

    // ---- Phase D: weighted sums (lane owns output dims 4*lane..4*lane+3)
    const int hbase = lane >> 2;           // head of this lane's output dims
    const int sidx = lane & 15;
    float4 acc = make_float4(0.f, 0.f, 0.f, 0.f);
    float sdl[8], ssl[4];
#pragma unroll
    for (int r = 0; r < 8; r++) sdl[r] = 0.f;
#pragma unroll
    for (int r = 0; r < 4; r++) ssl[r] = 0.f;
#pragma unroll 4
    for (int k = 0; k < 32; k++) {
        int j = s.jb[k];
        float a = s.attn[k * 9 + hbase];
        float4 mv = *(const float4*)(mvg + (long)j * 128 + lane * 4);
        acc.x += a * mv.x; acc.y += a * mv.y;
        acc.z += a * mv.z; acc.w += a * mv.w;
        float dv = s.dist[k * 33 + lane];
#pragma unroll
        for (int r = 0; r < 8; r++) sdl[r] += s.attn[k * 9 + r] * dv;
        float sv = s.seq[k * 17 + sidx];
#pragma unroll
        for (int r = 0; r < 4; r++) {
            int h2 = (lane >> 4) + 2 * r;
            ssl[r] += s.attn[k * 9 + h2] * sv;
        }
    }
#pragma unroll
    for (int r = 0; r < 8; r++) s.sd[r * 32 + lane] = sdl[r];
#pragma unroll
    for (int r = 0; r < 4; r++) s.ss[lane + 32 * r] = ssl[r];
    __syncwarp();

    // ---- Phase D2: out += sd @ WvD + ss @ WvS + bv
    {
        const int i0 = lane * 4;
        float4 o = *(const float4*)(bv + i0);
        o.x += acc.x; o.y += acc.y; o.z += acc.z; o.w += acc.w;
#pragma unroll 8
        for (int d = 0; d < 32; d++) {
            float sdv = s.sd[hbase * 32 + d];
            float4 wv = *(const float4*)(Wv + (128 + d) * 128 + i0);
            o.x += sdv * wv.x; o.y += sdv * wv.y;
            o.z += sdv * wv.z; o.w += sdv * wv.w;
        }
#pragma unroll 8
        for (int j = 0; j < 16; j++) {
            float ssv = s.ss[hbase * 16 + j];
            float4 wv = *(const float4*)(Wv + (160 + j) * 128 + i0);
            o.x += ssv * wv.x; o.y += ssv * wv.y;
            o.z += ssv * wv.z; o.w += ssv * wv.w;
        }
        *(float4*)(s.outv + i0) = o;
    }
    __syncwarp();

    // ---- Phase E: result = features + outv @ Wo + bo
    {
        const int i0 = lane * 4;
        float4 r = *(const float4*)(bo + i0);
        float4 f = *(const float4*)(features + n * 128 + i0);
        r.x += f.x; r.y += f.y; r.z += f.z; r.w += f.w;
#pragma unroll 8
        for (int i = 0; i < 128; i++) {
            float ov = s.outv[i];
            float4 wo = *(const float4*)(Wo + i * 128 + i0);
            r.x += ov * wo.x; r.y += ov * wo.y;
            r.z += ov * wo.z; r.w += ov * wo.w;
        }
        *(float4*)(out + n * 128 + i0) = r;
    }
}

// ---------------- launch ----------------
extern "C" void kernel_launch(void* const* d_in, const int* in_sizes, int n_in,
                              void* d_out, int out_size)
{
    const float* features = (const float*)d_in[0];
    const float* distances = (const float*)d_in[1];
    const float* sequence = (const float*)d_in[2];
    const float* encoder = (const float*)d_in[3];
    const int*   idx = (const int*)d_in[4];
    const float* W1 = (const float*)d_in[5];
    const float* b1 = (const float*)d_in[6];
    const float* W2 = (const float*)d_in[7];
    const float* b2 = (const float*)d_in[8];
    const float* W3 = (const float*)d_in[9];
    const float* b3 = (const float*)d_in[10];
    const float* Wq = (const float*)d_in[11];
    const float* bq = (const float*)d_in[12];
    const float* Wk = (const float*)d_in[13];
    const float* bk = (const float*)d_in[14];
    const float* Wv = (const float*)d_in[15];
    const float* bv = (const float*)d_in[16];
    const float* Wo = (const float*)d_in[17];
    const float* bo = (const float*)d_in[18];

    float *h1, *h2, *msg, *q, *mk, *mv;
    cudaGetSymbolAddress((void**)&h1, g_h1);
    cudaGetSymbolAddress((void**)&h2, g_h2);
    cudaGetSymbolAddress((void**)&msg, g_msg);
    cudaGetSymbolAddress((void**)&q, g_q);
    cudaGetSymbolAddress((void**)&mk, g_mk);
    cudaGetSymbolAddress((void**)&mv, g_mv);

    const int gb = N_NODES / 64;  // 256 blocks
    // h1 = relu(relu(features) @ W1 + b1)
    gemm128<1, 1, 1, 0><<<gb, 256>>>(features, W1, b1, nullptr, h1);
    // h2 = relu(h1 @ W2 + b2)
    gemm128<0, 1, 1, 0><<<gb, 256>>>(h1, W2, b2, nullptr, h2);
    // msg = relu(h2 @ W3 + b3) + encoder
    gemm128<0, 1, 1, 1><<<gb, 256>>>(h2, W3, b3, encoder, msg);
    // q = features @ Wq + bq
    gemm128<0, 0, 1, 0><<<gb, 256>>>(features, Wq, bq, nullptr, q);
    // msgK = msg @ Wk[0:128,:]   (gather-commute: nb@WkN == (msg@WkN)[idx])
    gemm128<0, 0, 0, 0><<<gb, 256>>>(msg, Wk, nullptr, nullptr, mk);
    // msgV = msg @ Wv[0:128,:]
    gemm128<0, 0, 0, 0><<<gb, 256>>>(msg, Wv, nullptr, nullptr, mv);
    // fused neighbor attention + output projection + residual
    attn_kernel<<<N_NODES / 4, 128>>>(features, distances, sequence, idx,
                                      q, mk, mv, Wk, bk, Wv, bv, Wo, bo,
                                      (float*)d_out);
}

// round 3
// speedup vs baseline: 1.0355x; 1.0355x over previous
#include <cuda_runtime.h>

#define N_NODES 16384
#define SZ 128
#define KNB 32

// ---------------- scratch (static device globals; no allocation) -----------
__device__ float g_h1[N_NODES * SZ];
__device__ float g_h2[N_NODES * SZ];
__device__ float g_msg[N_NODES * SZ];
__device__ float g_q[N_NODES * SZ];
__device__ float g_mk[N_NODES * SZ];
__device__ float g_mv[N_NODES * SZ];
__device__ float g_att[N_NODES * SZ];

// ---------------- dense 128-dim GEMM: C[N,128] = f(A[N,128] @ W[128,128] + b) (+ add)
// BM=64, BN=128, BK=32, 256 threads, each thread 8x4 outputs.
template <int RELU_IN, int RELU_OUT, int HAS_BIAS, int HAS_ADD>
__global__ __launch_bounds__(256) void gemm128(
    const float* __restrict__ A, const float* __restrict__ W,
    const float* __restrict__ bias, const float* __restrict__ add,
    float* __restrict__ C)
{
    __shared__ float As[32 * 64];    // [k][row]
    __shared__ float Ws[32 * 128];   // [k][col]
    const int t = threadIdx.x;
    const int tx = t & 31;           // col group: cols tx*4 .. tx*4+3
    const int ty = t >> 5;           // row group: rows ty*8 .. ty*8+7
    const int row0 = blockIdx.x * 64;

    float acc[8][4];
#pragma unroll
    for (int r = 0; r < 8; r++)
#pragma unroll
        for (int c = 0; c < 4; c++) acc[r][c] = 0.0f;

    for (int kt = 0; kt < 4; kt++) {
        const int kk0 = kt * 32;
        __syncthreads();
        // load A tile 64x32 (store transposed [k][row])
#pragma unroll
        for (int i = 0; i < 2; i++) {
            int f = t + i * 256;
            int r = f >> 3, c4 = f & 7;
            float4 v = *(const float4*)(A + (row0 + r) * 128 + kk0 + c4 * 4);
            if (RELU_IN) {
                v.x = fmaxf(v.x, 0.0f); v.y = fmaxf(v.y, 0.0f);
                v.z = fmaxf(v.z, 0.0f); v.w = fmaxf(v.w, 0.0f);
            }
            As[(c4 * 4 + 0) * 64 + r] = v.x;
            As[(c4 * 4 + 1) * 64 + r] = v.y;
            As[(c4 * 4 + 2) * 64 + r] = v.z;
            As[(c4 * 4 + 3) * 64 + r] = v.w;
        }
        // load W tile 32x128
#pragma unroll
        for (int i = 0; i < 4; i++) {
            int f = t + i * 256;
            int kr = f >> 5, c4 = f & 31;
            *(float4*)(Ws + kr * 128 + c4 * 4) =
                *(const float4*)(W + (kk0 + kr) * 128 + c4 * 4);
        }
        __syncthreads();
#pragma unroll
        for (int kk = 0; kk < 32; kk++) {
            float4 a0 = *(const float4*)(As + kk * 64 + ty * 8);
            float4 a1 = *(const float4*)(As + kk * 64 + ty * 8 + 4);
            float4 w  = *(const float4*)(Ws + kk * 128 + tx * 4);
            float ar[8] = {a0.x, a0.y, a0.z, a0.w, a1.x, a1.y, a1.z, a1.w};
#pragma unroll
            for (int r = 0; r < 8; r++) {
                acc[r][0] += ar[r] * w.x;
                acc[r][1] += ar[r] * w.y;
                acc[r][2] += ar[r] * w.z;
                acc[r][3] += ar[r] * w.w;
            }
        }
    }

    float4 bz = make_float4(0.f, 0.f, 0.f, 0.f);
    if (HAS_BIAS) bz = *(const float4*)(bias + tx * 4);
#pragma unroll
    for (int r = 0; r < 8; r++) {
        int gr = row0 + ty * 8 + r;
        float4 o;
        o.x = acc[r][0] + bz.x;
        o.y = acc[r][1] + bz.y;
        o.z = acc[r][2] + bz.z;
        o.w = acc[r][3] + bz.w;
        if (RELU_OUT) {
            o.x = fmaxf(o.x, 0.0f); o.y = fmaxf(o.y, 0.0f);
            o.z = fmaxf(o.z, 0.0f); o.w = fmaxf(o.w, 0.0f);
        }
        if (HAS_ADD) {
            float4 av = *(const float4*)(add + gr * 128 + tx * 4);
            o.x += av.x; o.y += av.y; o.z += av.z; o.w += av.w;
        }
        *(float4*)(C + gr * 128 + tx * 4) = o;
    }
}

// ---------------- per-node attention: 1 warp per node, lane <-> neighbor (K=32)
// dist/seq read directly from global (both access patterns coalesced; 2nd read
// hits L1). Phase E (out-projection) moved to a dense GEMM afterwards.
struct WarpSmem {
    float q[128];
    float ud[8 * 32];      // u_dist[h][d] = WkD^T q per head
    float us[8 * 16];      // u_seq[h][s]
    float c0[8];           // q . bk per head
    float attn[32 * 9];    // [k][h], pad 9
    float sd[8 * 32];      // sum_k attn*dist
    float ss[8 * 16];      // sum_k attn*seq
    int   jb[32];
};

__global__ __launch_bounds__(256, 4) void attn_kernel(
    const float* __restrict__ dist_g, const float* __restrict__ seq_g,
    const int* __restrict__ idx, const float* __restrict__ qg,
    const float* __restrict__ mkg, const float* __restrict__ mvg,
    const float* __restrict__ Wk, const float* __restrict__ bk,
    const float* __restrict__ Wv, const float* __restrict__ bv,
    float* __restrict__ att_out)
{
    __shared__ WarpSmem S[8];
    const int lane = threadIdx.x & 31;
    const int w = threadIdx.x >> 5;
    WarpSmem& s = S[w];
    const int n = blockIdx.x * 8 + w;

    // ---- Phase A: stage q + neighbor indices
    {
        float4 qv = ((const float4*)(qg + n * 128))[lane];
        *(float4*)(s.q + lane * 4) = qv;
        s.jb[lane] = idx[n * 32 + lane];
    }
    __syncwarp();

    // ---- Phase B: u = W^T q folds (dist / seq / bias)
#pragma unroll
    for (int r = 0; r < 8; r++) {
        int h = r, d = lane;
        const float* wr = Wk + (128 + d) * 128 + h * 16;
        const float* qh = s.q + h * 16;
        float a = 0.f;
#pragma unroll
        for (int j = 0; j < 16; j++) a += wr[j] * qh[j];
        s.ud[h * 32 + d] = a;
    }
#pragma unroll
    for (int r = 0; r < 4; r++) {
        int o = lane + 32 * r;             // o = h*16+sc
        int h = o >> 4, sc = o & 15;
        const float* wr = Wk + (160 + sc) * 128 + h * 16;
        const float* qh = s.q + h * 16;
        float a = 0.f;
#pragma unroll
        for (int j = 0; j < 16; j++) a += wr[j] * qh[j];
        s.us[o] = a;
    }
    if (lane < 8) {
        const float* qh = s.q + lane * 16;
        const float* br = bk + lane * 16;
        float a = 0.f;
#pragma unroll
        for (int j = 0; j < 16; j++) a += br[j] * qh[j];
        s.c0[lane] = a;
    }
    __syncwarp();

    // ---- Phase C: logits (lane = neighbor k) + softmax over lanes
    float lg[8];
#pragma unroll
    for (int h = 0; h < 8; h++) lg[h] = 0.f;
    {
        const int jrow = s.jb[lane];
        const float4* mk4 = (const float4*)(mkg + (long)jrow * 128);
#pragma unroll
        for (int i4 = 0; i4 < 32; i4++) {
            float4 m = mk4[i4];
            float4 qv = *(const float4*)(s.q + i4 * 4);
            int h = i4 >> 2;
            lg[h] += qv.x * m.x + qv.y * m.y + qv.z * m.z + qv.w * m.w;
        }
        const float4* dg4 = (const float4*)(dist_g + (long)n * 1024 + lane * 32);
#pragma unroll
        for (int i4 = 0; i4 < 8; i4++) {
            float4 dv = dg4[i4];
#pragma unroll
            for (int h = 0; h < 8; h++) {
                float4 u = *(const float4*)(s.ud + h * 32 + i4 * 4);
                lg[h] += dv.x * u.x + dv.y * u.y + dv.z * u.z + dv.w * u.w;
            }
        }
        const float4* sg4 = (const float4*)(seq_g + (long)n * 512 + lane * 16);
#pragma unroll
        for (int i4 = 0; i4 < 4; i4++) {
            float4 sv = sg4[i4];
#pragma unroll
            for (int h = 0; h < 8; h++) {
                float4 u = *(const float4*)(s.us + h * 16 + i4 * 4);
                lg[h] += sv.x * u.x + sv.y * u.y + sv.z * u.z + sv.w * u.w;
            }
        }
    }
#pragma unroll
    for (int h = 0; h < 8; h++) lg[h] = 0.25f * (lg[h] + s.c0[h]);
#pragma unroll
    for (int h = 0; h < 8; h++) {
        float m = lg[h];
#pragma unroll
        for (int o = 16; o > 0; o >>= 1) m = fmaxf(m, __shfl_xor_sync(~0u, m, o));
        float e = __expf(lg[h] - m);
        float sm = e;
#pragma unroll
        for (int o = 16; o > 0; o >>= 1) sm += __shfl_xor_sync(~0u, sm, o);
        s.attn[lane * 9 + h] = e / sm;
    }
    __syncwarp();

    // ---- Phase D: weighted sums (lane owns output dims 4*lane..4*lane+3)
    const int hbase = lane >> 2;           // head of this lane's output dims
    const int sidx = lane & 15;
    float4 acc = make_float4(0.f, 0.f, 0.f, 0.f);
    float sdl[8], ssl[4];
#pragma unroll
    for (int r = 0; r < 8; r++) sdl[r] = 0.f;
#pragma unroll
    for (int r = 0; r < 4; r++) ssl[r] = 0.f;
#pragma unroll 4
    for (int k = 0; k < 32; k++) {
        int j = s.jb[k];
        float a = s.attn[k * 9 + hbase];
        float4 mv = *(const float4*)(mvg + (long)j * 128 + lane * 4);
        acc.x += a * mv.x; acc.y += a * mv.y;
        acc.z += a * mv.z; acc.w += a * mv.w;
        float dv = dist_g[(long)n * 1024 + k * 32 + lane];      // L1 hit
#pragma unroll
        for (int r = 0; r < 8; r++) sdl[r] += s.attn[k * 9 + r] * dv;
        float sv = seq_g[(long)n * 512 + k * 16 + sidx];        // L1 hit
#pragma unroll
        for (int r = 0; r < 4; r++) {
            int h2 = (lane >> 4) + 2 * r;
            ssl[r] += s.attn[k * 9 + h2] * sv;
        }
    }
#pragma unroll
    for (int r = 0; r < 8; r++) s.sd[r * 32 + lane] = sdl[r];
#pragma unroll
    for (int r = 0; r < 4; r++) s.ss[lane + 32 * r] = ssl[r];
    __syncwarp();

    // ---- Phase D2: outv = acc + sd @ WvD + ss @ WvS + bv  -> global (GEMM input)
    {
        const int i0 = lane * 4;
        float4 o = *(const float4*)(bv + i0);
        o.x += acc.x; o.y += acc.y; o.z += acc.z; o.w += acc.w;
#pragma unroll 8
        for (int d = 0; d < 32; d++) {
            float sdv = s.sd[hbase * 32 + d];
            float4 wv = *(const float4*)(Wv + (128 + d) * 128 + i0);
            o.x += sdv * wv.x; o.y += sdv * wv.y;
            o.z += sdv * wv.z; o.w += sdv * wv.w;
        }
#pragma unroll 8
        for (int j = 0; j < 16; j++) {
            float ssv = s.ss[hbase * 16 + j];
            float4 wv = *(const float4*)(Wv + (160 + j) * 128 + i0);
            o.x += ssv * wv.x; o.y += ssv * wv.y;
            o.z += ssv * wv.z; o.w += ssv * wv.w;
        }
        *(float4*)(att_out + (long)n * 128 + i0) = o;
    }
}

// ---------------- launch ----------------
extern "C" void kernel_launch(void* const* d_in, const int* in_sizes, int n_in,
                              void* d_out, int out_size)
{
    const float* features = (const float*)d_in[0];
    const float* distances = (const float*)d_in[1];
    const float* sequence = (const float*)d_in[2];
    const float* encoder = (const float*)d_in[3];
    const int*   idx = (const int*)d_in[4];
    const float* W1 = (const float*)d_in[5];
    const float* b1 = (const float*)d_in[6];
    const float* W2 = (const float*)d_in[7];
    const float* b2 = (const float*)d_in[8];
    const float* W3 = (const float*)d_in[9];
    const float* b3 = (const float*)d_in[10];
    const float* Wq = (const float*)d_in[11];
    const float* bq = (const float*)d_in[12];
    const float* Wk = (const float*)d_in[13];
    const float* bk = (const float*)d_in[14];
    const float* Wv = (const float*)d_in[15];
    const float* bv = (const float*)d_in[16];
    const float* Wo = (const float*)d_in[17];
    const float* bo = (const float*)d_in[18];

    float *h1, *h2, *msg, *q, *mk, *mv, *att;
    cudaGetSymbolAddress((void**)&h1, g_h1);
    cudaGetSymbolAddress((void**)&h2, g_h2);
    cudaGetSymbolAddress((void**)&msg, g_msg);
    cudaGetSymbolAddress((void**)&q, g_q);
    cudaGetSymbolAddress((void**)&mk, g_mk);
    cudaGetSymbolAddress((void**)&mv, g_mv);
    cudaGetSymbolAddress((void**)&att, g_att);

    const int gb = N_NODES / 64;  // 256 blocks
    // h1 = relu(relu(features) @ W1 + b1)
    gemm128<1, 1, 1, 0><<<gb, 256>>>(features, W1, b1, nullptr, h1);
    // h2 = relu(h1 @ W2 + b2)
    gemm128<0, 1, 1, 0><<<gb, 256>>>(h1, W2, b2, nullptr, h2);
    // msg = relu(h2 @ W3 + b3) + encoder
    gemm128<0, 1, 1, 1><<<gb, 256>>>(h2, W3, b3, encoder, msg);
    // q = features @ Wq + bq
    gemm128<0, 0, 1, 0><<<gb, 256>>>(features, Wq, bq, nullptr, q);
    // msgK = msg @ Wk[0:128,:]   (gather-commute: nb@WkN == (msg@WkN)[idx])
    gemm128<0, 0, 0, 0><<<gb, 256>>>(msg, Wk, nullptr, nullptr, mk);
    // msgV = msg @ Wv[0:128,:]
    gemm128<0, 0, 0, 0><<<gb, 256>>>(msg, Wv, nullptr, nullptr, mv);
    // fused neighbor attention -> att (pre-projection output)
    attn_kernel<<<N_NODES / 8, 256>>>(distances, sequence, idx,
                                      q, mk, mv, Wk, bk, Wv, bv, att);
    // out = features + att @ Wo + bo
    gemm128<0, 0, 1, 1><<<gb, 256>>>(att, Wo, bo, features, (float*)d_out);
}

// round 4
// speedup vs baseline: 1.9896x; 1.9214x over previous
#include <cuda_runtime.h>

#define N_NODES 16384
#define SZ 128

// ---------------- scratch (static device globals; no allocation) -----------
__device__ float g_h1[N_NODES * SZ];
__device__ float g_h2[N_NODES * SZ];
__device__ float g_msg[N_NODES * SZ];
__device__ float g_q[N_NODES * SZ];
__device__ float g_mk[N_NODES * SZ];
__device__ float g_mv[N_NODES * SZ];
__device__ float g_att[N_NODES * SZ];

// ---------------- dense 128-dim GEMM: C[N,128] = f(A[N,128] @ W[128,128] + b) (+ add)
template <int RELU_IN, int RELU_OUT, int HAS_BIAS, int HAS_ADD>
__global__ __launch_bounds__(256) void gemm128(
    const float* __restrict__ A, const float* __restrict__ W,
    const float* __restrict__ bias, const float* __restrict__ add,
    float* __restrict__ C)
{
    __shared__ float As[32 * 64];    // [k][row]
    __shared__ float Ws[32 * 128];   // [k][col]
    const int t = threadIdx.x;
    const int tx = t & 31;
    const int ty = t >> 5;
    const int row0 = blockIdx.x * 64;

    float acc[8][4];
#pragma unroll
    for (int r = 0; r < 8; r++)
#pragma unroll
        for (int c = 0; c < 4; c++) acc[r][c] = 0.0f;

    for (int kt = 0; kt < 4; kt++) {
        const int kk0 = kt * 32;
        __syncthreads();
#pragma unroll
        for (int i = 0; i < 2; i++) {
            int f = t + i * 256;
            int r = f >> 3, c4 = f & 7;
            float4 v = *(const float4*)(A + (row0 + r) * 128 + kk0 + c4 * 4);
            if (RELU_IN) {
                v.x = fmaxf(v.x, 0.0f); v.y = fmaxf(v.y, 0.0f);
                v.z = fmaxf(v.z, 0.0f); v.w = fmaxf(v.w, 0.0f);
            }
            As[(c4 * 4 + 0) * 64 + r] = v.x;
            As[(c4 * 4 + 1) * 64 + r] = v.y;
            As[(c4 * 4 + 2) * 64 + r] = v.z;
            As[(c4 * 4 + 3) * 64 + r] = v.w;
        }
#pragma unroll
        for (int i = 0; i < 4; i++) {
            int f = t + i * 256;
            int kr = f >> 5, c4 = f & 31;
            *(float4*)(Ws + kr * 128 + c4 * 4) =
                *(const float4*)(W + (kk0 + kr) * 128 + c4 * 4);
        }
        __syncthreads();
#pragma unroll
        for (int kk = 0; kk < 32; kk++) {
            float4 a0 = *(const float4*)(As + kk * 64 + ty * 8);
            float4 a1 = *(const float4*)(As + kk * 64 + ty * 8 + 4);
            float4 w  = *(const float4*)(Ws + kk * 128 + tx * 4);
            float ar[8] = {a0.x, a0.y, a0.z, a0.w, a1.x, a1.y, a1.z, a1.w};
#pragma unroll
            for (int r = 0; r < 8; r++) {
                acc[r][0] += ar[r] * w.x;
                acc[r][1] += ar[r] * w.y;
                acc[r][2] += ar[r] * w.z;
                acc[r][3] += ar[r] * w.w;
            }
        }
    }

    float4 bz = make_float4(0.f, 0.f, 0.f, 0.f);
    if (HAS_BIAS) bz = *(const float4*)(bias + tx * 4);
#pragma unroll
    for (int r = 0; r < 8; r++) {
        int gr = row0 + ty * 8 + r;
        float4 o;
        o.x = acc[r][0] + bz.x;
        o.y = acc[r][1] + bz.y;
        o.z = acc[r][2] + bz.z;
        o.w = acc[r][3] + bz.w;
        if (RELU_OUT) {
            o.x = fmaxf(o.x, 0.0f); o.y = fmaxf(o.y, 0.0f);
            o.z = fmaxf(o.z, 0.0f); o.w = fmaxf(o.w, 0.0f);
        }
        if (HAS_ADD) {
            float4 av = *(const float4*)(add + gr * 128 + tx * 4);
            o.x += av.x; o.y += av.y; o.z += av.z; o.w += av.w;
        }
        *(float4*)(C + gr * 128 + tx * 4) = o;
    }
}

// ---------------- dual-output GEMM: C1 = A@W1, C2 = A@W2 (shared A tile) ----
__global__ __launch_bounds__(256) void gemm128_dual(
    const float* __restrict__ A, const float* __restrict__ W1g,
    const float* __restrict__ W2g, float* __restrict__ C1,
    float* __restrict__ C2)
{
    __shared__ float As[32 * 64];
    __shared__ float Ws1[32 * 128];
    __shared__ float Ws2[32 * 128];
    const int t = threadIdx.x;
    const int tx = t & 31;
    const int ty = t >> 5;
    const int row0 = blockIdx.x * 64;

    float acc1[8][4], acc2[8][4];
#pragma unroll
    for (int r = 0; r < 8; r++)
#pragma unroll
        for (int c = 0; c < 4; c++) { acc1[r][c] = 0.f; acc2[r][c] = 0.f; }

    for (int kt = 0; kt < 4; kt++) {
        const int kk0 = kt * 32;
        __syncthreads();
#pragma unroll
        for (int i = 0; i < 2; i++) {
            int f = t + i * 256;
            int r = f >> 3, c4 = f & 7;
            float4 v = *(const float4*)(A + (row0 + r) * 128 + kk0 + c4 * 4);
            As[(c4 * 4 + 0) * 64 + r] = v.x;
            As[(c4 * 4 + 1) * 64 + r] = v.y;
            As[(c4 * 4 + 2) * 64 + r] = v.z;
            As[(c4 * 4 + 3) * 64 + r] = v.w;
        }
#pragma unroll
        for (int i = 0; i < 4; i++) {
            int f = t + i * 256;
            int kr = f >> 5, c4 = f & 31;
            *(float4*)(Ws1 + kr * 128 + c4 * 4) =
                *(const float4*)(W1g + (kk0 + kr) * 128 + c4 * 4);
            *(float4*)(Ws2 + kr * 128 + c4 * 4) =
                *(const float4*)(W2g + (kk0 + kr) * 128 + c4 * 4);
        }
        __syncthreads();
#pragma unroll
        for (int kk = 0; kk < 32; kk++) {
            float4 a0 = *(const float4*)(As + kk * 64 + ty * 8);
            float4 a1 = *(const float4*)(As + kk * 64 + ty * 8 + 4);
            float4 w1 = *(const float4*)(Ws1 + kk * 128 + tx * 4);
            float4 w2 = *(const float4*)(Ws2 + kk * 128 + tx * 4);
            float ar[8] = {a0.x, a0.y, a0.z, a0.w, a1.x, a1.y, a1.z, a1.w};
#pragma unroll
            for (int r = 0; r < 8; r++) {
                acc1[r][0] += ar[r] * w1.x; acc1[r][1] += ar[r] * w1.y;
                acc1[r][2] += ar[r] * w1.z; acc1[r][3] += ar[r] * w1.w;
                acc2[r][0] += ar[r] * w2.x; acc2[r][1] += ar[r] * w2.y;
                acc2[r][2] += ar[r] * w2.z; acc2[r][3] += ar[r] * w2.w;
            }
        }
    }
#pragma unroll
    for (int r = 0; r < 8; r++) {
        int gr = row0 + ty * 8 + r;
        *(float4*)(C1 + gr * 128 + tx * 4) =
            make_float4(acc1[r][0], acc1[r][1], acc1[r][2], acc1[r][3]);
        *(float4*)(C2 + gr * 128 + tx * 4) =
            make_float4(acc2[r][0], acc2[r][1], acc2[r][2], acc2[r][3]);
    }
}

// ---------------- attention: 1 warp/node, ALL global loads warp-coalesced ----
struct WarpSmem {
    float dist[32 * 36];   // [k][d] pad-36 (16B-aligned rows, LDS.128-able)
    float seq[32 * 20];    // [k][s] pad-20
    float ud[8 * 32];      // WkD^T q per head
    float us[8 * 16];      // WkS^T q per head
    float c0[8];           // q . bk per head
    float lgk[32 * 9];     // logits then attn, [k][h] pad 9
    float sd[8 * 32];      // sum_k attn*dist
    float ss[8 * 16];      // sum_k attn*seq
    int   jb[32];
};                          // 11552 B

__global__ __launch_bounds__(128) void attn_kernel(
    const float* __restrict__ dist_g, const float* __restrict__ seq_g,
    const int* __restrict__ idx, const float* __restrict__ qg,
    const float* __restrict__ mkg, const float* __restrict__ mvg,
    const float* __restrict__ Wk, const float* __restrict__ bk,
    const float* __restrict__ Wv, const float* __restrict__ bv,
    float* __restrict__ att_out)
{
    __shared__ WarpSmem S[4];
    const int lane = threadIdx.x & 31;
    const int w = threadIdx.x >> 5;
    WarpSmem& s = S[w];
    const int n = blockIdx.x * 4 + w;

    // ---- Phase A: coalesced staging
    const float4 qv = ((const float4*)(qg + (long)n * 128))[lane];
    s.jb[lane] = idx[n * 32 + lane];
    {
        const float4* dg = (const float4*)(dist_g + (long)n * 1024);
#pragma unroll
        for (int it = 0; it < 8; it++) {
            int i4 = it * 32 + lane;
            float4 v = dg[i4];
            float* p = s.dist + (i4 >> 3) * 36 + (i4 & 7) * 4;
            p[0] = v.x; p[1] = v.y; p[2] = v.z; p[3] = v.w;
        }
        const float4* sg = (const float4*)(seq_g + (long)n * 512);
#pragma unroll
        for (int it = 0; it < 4; it++) {
            int i4 = it * 32 + lane;
            float4 v = sg[i4];
            float* p = s.seq + (i4 >> 2) * 20 + (i4 & 3) * 4;
            p[0] = v.x; p[1] = v.y; p[2] = v.z; p[3] = v.w;
        }
    }
    __syncwarp();

    // ---- Phase B: folds ud/us/c0 via coalesced row loads + 4-lane reduce
    const int h4 = lane >> 2;                // head owned by this lane group
#pragma unroll 8
    for (int r = 0; r < 48; r++) {
        float4 wv = *(const float4*)(Wk + (long)(128 + r) * 128 + lane * 4);
        float p = wv.x * qv.x + wv.y * qv.y + wv.z * qv.z + wv.w * qv.w;
        p += __shfl_xor_sync(~0u, p, 1);
        p += __shfl_xor_sync(~0u, p, 2);
        if ((lane & 3) == 0) {
            if (r < 32) s.ud[h4 * 32 + r] = p;
            else        s.us[h4 * 16 + (r - 32)] = p;
        }
    }
    {
        float4 wv = *(const float4*)(bk + lane * 4);
        float p = wv.x * qv.x + wv.y * qv.y + wv.z * qv.z + wv.w * qv.w;
        p += __shfl_xor_sync(~0u, p, 1);
        p += __shfl_xor_sync(~0u, p, 2);
        if ((lane & 3) == 0) s.c0[h4] = p;
    }
    __syncwarp();

    // ---- Phase C1: q . mk[jb[k]] (coalesced row load per k + 4-lane reduce)
#pragma unroll 8
    for (int k = 0; k < 32; k++) {
        int j = s.jb[k];
        float4 m = *(const float4*)(mkg + (long)j * 128 + lane * 4);
        float p = m.x * qv.x + m.y * qv.y + m.z * qv.z + m.w * qv.w;
        p += __shfl_xor_sync(~0u, p, 1);
        p += __shfl_xor_sync(~0u, p, 2);
        if ((lane & 3) == 0) s.lgk[k * 9 + h4] = p;
    }
    __syncwarp();

    // ---- Phase C2: dist/seq logit terms (lane = k) + softmax over lanes
    float lg[8];
    {
        float4 dr[8], sr[4];
#pragma unroll
        for (int i = 0; i < 8; i++) dr[i] = *(const float4*)(s.dist + lane * 36 + i * 4);
#pragma unroll
        for (int i = 0; i < 4; i++) sr[i] = *(const float4*)(s.seq + lane * 20 + i * 4);
#pragma unroll
        for (int h = 0; h < 8; h++) {
            float a = 0.f;
#pragma unroll
            for (int i = 0; i < 8; i++) {
                float4 u = *(const float4*)(s.ud + h * 32 + i * 4);
                a += dr[i].x * u.x + dr[i].y * u.y + dr[i].z * u.z + dr[i].w * u.w;
            }
#pragma unroll
            for (int i = 0; i < 4; i++) {
                float4 u = *(const float4*)(s.us + h * 16 + i * 4);
                a += sr[i].x * u.x + sr[i].y * u.y + sr[i].z * u.z + sr[i].w * u.w;
            }
            lg[h] = 0.25f * (s.lgk[lane * 9 + h] + a + s.c0[h]);
        }
    }
#pragma unroll
    for (int h = 0; h < 8; h++) {
        float m = lg[h];
#pragma unroll
        for (int o = 16; o > 0; o >>= 1) m = fmaxf(m, __shfl_xor_sync(~0u, m, o));
        float e = __expf(lg[h] - m);
        float sm = e;
#pragma unroll
        for (int o = 16; o > 0; o >>= 1) sm += __shfl_xor_sync(~0u, sm, o);
        s.lgk[lane * 9 + h] = e / sm;    // now attn weights
    }
    __syncwarp();

    // ---- Phase D: weighted sums (lane owns output dims 4*lane..4*lane+3)
    const int sidx = lane & 15;
    float4 acc = make_float4(0.f, 0.f, 0.f, 0.f);
    float sdl[8], ssl[4];
#pragma unroll
    for (int r = 0; r < 8; r++) sdl[r] = 0.f;
#pragma unroll
    for (int r = 0; r < 4; r++) ssl[r] = 0.f;
#pragma unroll 4
    for (int k = 0; k < 32; k++) {
        int j = s.jb[k];
        float a = s.lgk[k * 9 + h4];
        float4 mv = *(const float4*)(mvg + (long)j * 128 + lane * 4);
        acc.x += a * mv.x; acc.y += a * mv.y;
        acc.z += a * mv.z; acc.w += a * mv.w;
        float dv = s.dist[k * 36 + lane];
#pragma unroll
        for (int r = 0; r < 8; r++) sdl[r] += s.lgk[k * 9 + r] * dv;
        float sv = s.seq[k * 20 + sidx];
#pragma unroll
        for (int r = 0; r < 4; r++) {
            int h2 = (lane >> 4) + 2 * r;
            ssl[r] += s.lgk[k * 9 + h2] * sv;
        }
    }
#pragma unroll
    for (int r = 0; r < 8; r++) s.sd[r * 32 + lane] = sdl[r];
#pragma unroll
    for (int r = 0; r < 4; r++) s.ss[lane + 32 * r] = ssl[r];
    __syncwarp();

    // ---- Phase D2: outv = acc + sd @ WvD + ss @ WvS + bv  -> global
    {
        const int i0 = lane * 4;
        float4 o = *(const float4*)(bv + i0);
        o.x += acc.x; o.y += acc.y; o.z += acc.z; o.w += acc.w;
#pragma unroll 8
        for (int d = 0; d < 32; d++) {
            float sdv = s.sd[h4 * 32 + d];
            float4 wv = *(const float4*)(Wv + (long)(128 + d) * 128 + i0);
            o.x += sdv * wv.x; o.y += sdv * wv.y;
            o.z += sdv * wv.z; o.w += sdv * wv.w;
        }
#pragma unroll 8
        for (int j = 0; j < 16; j++) {
            float ssv = s.ss[h4 * 16 + j];
            float4 wv = *(const float4*)(Wv + (long)(160 + j) * 128 + i0);
            o.x += ssv * wv.x; o.y += ssv * wv.y;
            o.z += ssv * wv.z; o.w += ssv * wv.w;
        }
        *(float4*)(att_out + (long)n * 128 + i0) = o;
    }
}

// ---------------- launch ----------------
extern "C" void kernel_launch(void* const* d_in, const int* in_sizes, int n_in,
                              void* d_out, int out_size)
{
    const float* features = (const float*)d_in[0];
    const float* distances = (const float*)d_in[1];
    const float* sequence = (const float*)d_in[2];
    const float* encoder = (const float*)d_in[3];
    const int*   idx = (const int*)d_in[4];
    const float* W1 = (const float*)d_in[5];
    const float* b1 = (const float*)d_in[6];
    const float* W2 = (const float*)d_in[7];
    const float* b2 = (const float*)d_in[8];
    const float* W3 = (const float*)d_in[9];
    const float* b3 = (const float*)d_in[10];
    const float* Wq = (const float*)d_in[11];
    const float* bq = (const float*)d_in[12];
    const float* Wk = (const float*)d_in[13];
    const float* bk = (const float*)d_in[14];
    const float* Wv = (const float*)d_in[15];
    const float* bv = (const float*)d_in[16];
    const float* Wo = (const float*)d_in[17];
    const float* bo = (const float*)d_in[18];

    float *h1, *h2, *msg, *q, *mk, *mv, *att;
    cudaGetSymbolAddress((void**)&h1, g_h1);
    cudaGetSymbolAddress((void**)&h2, g_h2);
    cudaGetSymbolAddress((void**)&msg, g_msg);
    cudaGetSymbolAddress((void**)&q, g_q);
    cudaGetSymbolAddress((void**)&mk, g_mk);
    cudaGetSymbolAddress((void**)&mv, g_mv);
    cudaGetSymbolAddress((void**)&att, g_att);

    const int gb = N_NODES / 64;  // 256 blocks
    gemm128<1, 1, 1, 0><<<gb, 256>>>(features, W1, b1, nullptr, h1);   // 0
    gemm128<0, 1, 1, 0><<<gb, 256>>>(h1, W2, b2, nullptr, h2);         // 1
    gemm128<0, 1, 1, 1><<<gb, 256>>>(h2, W3, b3, encoder, msg);        // 2
    gemm128<0, 0, 1, 0><<<gb, 256>>>(features, Wq, bq, nullptr, q);    // 3
    gemm128_dual<<<gb, 256>>>(msg, Wk, Wv, mk, mv);                    // 4
    attn_kernel<<<N_NODES / 4, 128>>>(distances, sequence, idx,        // 5 (profiled)
                                      q, mk, mv, Wk, bk, Wv, bv, att);
    gemm128<0, 0, 1, 1><<<gb, 256>>>(att, Wo, bo, features, (float*)d_out); // 6
}